// round 12
// baseline (speedup 1.0000x reference)
#include <cuda_runtime.h>
#include <cuda_bf16.h>
#include <cstdint>
#include <math.h>

#define TOKENS 8192
#define HDIM   1024
#define NOSC   64
#define TWO_N  128
#define SEQ    2048

// ---------------- scratch (static device memory; no allocations) ----------------
static __device__ __nv_bfloat16 g_xb [TOKENS * HDIM];
static __device__ __nv_bfloat16 g_h  [TOKENS * HDIM];
static __device__ __nv_bfloat16 g_h2 [TOKENS * HDIM];
static __device__ float         g_osc[TOKENS * TWO_N];
static __device__ __nv_bfloat16 g_comb[TOKENS * TWO_N];
// weights stored TRANSPOSED: [N, K] bf16 (so GEMM B-loads are K-major, no ldmatrix.trans)
static __device__ __nv_bfloat16 g_W1t[HDIM * HDIM];
static __device__ __nv_bfloat16 g_W2t[TWO_N * HDIM];
static __device__ __nv_bfloat16 g_W3t[HDIM * TWO_N];
static __device__ __nv_bfloat16 g_W4t[HDIM * HDIM];
static __device__ float         g_csum[NOSC];

// ---------------- PTX helpers ----------------
__device__ __forceinline__ void cp_async16(void* s, const void* g) {
    uint32_t sa = (uint32_t)__cvta_generic_to_shared(s);
    asm volatile("cp.async.cg.shared.global [%0], [%1], 16;\n" :: "r"(sa), "l"(g));
}
__device__ __forceinline__ void cp_commit() {
    asm volatile("cp.async.commit_group;\n" ::: "memory");
}
template <int N>
__device__ __forceinline__ void cp_wait() {
    asm volatile("cp.async.wait_group %0;\n" :: "n"(N) : "memory");
}
__device__ __forceinline__ void ldmatrix_x4(uint32_t* r, const void* p) {
    uint32_t a = (uint32_t)__cvta_generic_to_shared(p);
    asm volatile("ldmatrix.sync.aligned.m8n8.x4.shared.b16 {%0,%1,%2,%3}, [%4];\n"
        : "=r"(r[0]), "=r"(r[1]), "=r"(r[2]), "=r"(r[3]) : "r"(a));
}
// NON-volatile: ptxas schedules by register dependencies.
__device__ __forceinline__ void mma16816(float* d, const uint32_t* a, uint32_t b0, uint32_t b1) {
    asm("mma.sync.aligned.m16n8k16.row.col.f32.bf16.bf16.f32 "
        "{%0,%1,%2,%3}, {%4,%5,%6,%7}, {%8,%9}, {%0,%1,%2,%3};\n"
        : "+f"(d[0]), "+f"(d[1]), "+f"(d[2]), "+f"(d[3])
        : "r"(a[0]), "r"(a[1]), "r"(a[2]), "r"(a[3]), "r"(b0), "r"(b1));
}

// ---------------- fused prep: x convert + 4 weight TRANSPOSES + coupling csum ----------------
// grid = 8192 (x) + 1024 (W1) + 128 (W2) + 128 (W3) + 1024 (W4) + 1 (csum) = 10497
__global__ void k_prep(const float* __restrict__ x,
                       const float* __restrict__ W1, const float* __restrict__ W2,
                       const float* __restrict__ W3, const float* __restrict__ W4,
                       const float* __restrict__ coupling) {
    const int b = blockIdx.x;
    const int tid = threadIdx.x;
    if (b < 8192) {
        int i = b * 1024 + tid * 4;
        float4 v = *reinterpret_cast<const float4*>(x + i);
        *reinterpret_cast<__nv_bfloat162*>(g_xb + i)     = __floats2bfloat162_rn(v.x, v.y);
        *reinterpret_cast<__nv_bfloat162*>(g_xb + i + 2) = __floats2bfloat162_rn(v.z, v.w);
        return;
    }
    if (b == 10496) {
        int m = tid;
        if (m < NOSC) {
            float s = 0.f;
            #pragma unroll
            for (int j = 0; j < NOSC; j++) s += coupling[m * NOSC + j];
            g_csum[m] = s;
        }
        return;
    }
    // transpose tile: W [K,N] f32 -> Wt [N,K] bf16
    const float* W; __nv_bfloat16* Wt; int K, N, tn, tk;
    if (b < 9216)      { W = W1; Wt = g_W1t; K = 1024; N = 1024; int t = b - 8192; tn = t & 31;  tk = t >> 5; }
    else if (b < 9344) { W = W2; Wt = g_W2t; K = 1024; N = 128;  int t = b - 9216; tn = t & 3;   tk = t >> 2; }
    else if (b < 9472) { W = W3; Wt = g_W3t; K = 128;  N = 1024; int t = b - 9344; tn = t & 31;  tk = t >> 5; }
    else               { W = W4; Wt = g_W4t; K = 1024; N = 1024; int t = b - 9472; tn = t & 31;  tk = t >> 5; }

    __shared__ float tile[32][33];
    const int tx = tid & 31, ty = tid >> 5;     // 256 threads: 8 rows per pass
    #pragma unroll
    for (int i = 0; i < 4; i++) {
        int r = ty + i * 8;                     // k within tile
        tile[r][tx] = W[(size_t)(tk * 32 + r) * N + tn * 32 + tx];
    }
    __syncthreads();
    #pragma unroll
    for (int i = 0; i < 4; i++) {
        int r = ty + i * 8;                     // n within tile
        Wt[(size_t)(tn * 32 + r) * K + tk * 32 + tx] = __float2bfloat16(tile[tx][r]);
    }
}

// ---------------- oscillator dynamics: 1 warp per token, 2 osc per lane ----------------
__global__ void k_dynamics(const float* __restrict__ t, const float* __restrict__ Wt,
                           const float* __restrict__ bt, const float* __restrict__ freq,
                           const float* __restrict__ mu_p) {
    const int tok  = blockIdx.x * 8 + (threadIdx.x >> 5);
    const int lane = threadIdx.x & 31;
    const int i0 = lane, i1 = lane + 32;
    __nv_bfloat16* out = g_comb + (size_t)tok * TWO_N;

    if ((tok & (SEQ - 1)) == 0) {
        const float* cur = g_osc + (size_t)tok * TWO_N;
        out[i0]        = __float2bfloat16(cur[i0]);
        out[i1]        = __float2bfloat16(cur[i1]);
        out[NOSC + i0] = __float2bfloat16(cur[NOSC + i0]);
        out[NOSC + i1] = __float2bfloat16(cur[NOSC + i1]);
        return;
    }

    const float* prev = g_osc + (size_t)(tok - 1) * TWO_N;
    float p0 = prev[i0], p1 = prev[i1];
    float a0 = prev[NOSC + i0], a1 = prev[NOSC + i1];
    float sp0, cp0, sp1, cp1;
    sincosf(p0, &sp0, &cp0);
    sincosf(p1, &sp1, &cp1);

    float cs0 = g_csum[i0], cs1 = g_csum[i1];
    float vc = cs0 * cp0 + cs1 * cp1;
    float vs = cs0 * sp0 + cs1 * sp1;
    #pragma unroll
    for (int o = 16; o > 0; o >>= 1) {
        vc += __shfl_xor_sync(0xffffffffu, vc, o);
        vs += __shfl_xor_sync(0xffffffffu, vs, o);
    }

    const float tv = t[tok];
    const float mu = *mu_p;

    float cpl0 = sp0 * vc - cp0 * vs;
    float cpl1 = sp1 * vc - cp1 * vs;
    float d0 = freq[i0] + cpl0 * 0.1f + (tv * Wt[i0] + bt[i0]) * 0.1f;
    float d1 = freq[i1] + cpl1 * 0.1f + (tv * Wt[i1] + bt[i1]) * 0.1f;
    float pn0 = p0 + d0 * 0.1f;
    float pn1 = p1 + d1 * 0.1f;

    float da0 = (mu - 0.1f) * a0 - a0 * a0 * a0;
    float da1 = (mu - 0.1f) * a1 - a1 * a1 * a1;
    float an0 = tanhf(a0 + da0 * 0.1f);
    float an1 = tanhf(a1 + da1 * 0.1f);

    out[i0]        = __float2bfloat16(pn0);
    out[i1]        = __float2bfloat16(pn1);
    out[NOSC + i0] = __float2bfloat16(an0);
    out[NOSC + i1] = __float2bfloat16(an1);
}

// ---------------- tiled bf16 mma.sync GEMM, epoch pipeline, NO ldmatrix.trans ----------------
// A [M,K] bf16 row-major; Bt [N,K] bf16 row-major (pre-transposed weights).
// Both operands K-major in smem (stride 40), all fragments via non-trans ldmatrix.x4.
// 128-thread CTAs, warp grid 2x2, warp tile (BM/2) x (BN/2); one wait+sync per 64 K.
// EPI: 0 = bias+leaky_relu -> bf16 ; 1 = bias -> f32 ; 2 = resid + 0.1*(acc+bias) -> f32
#define BK 32
#define KSTR 40     // K-major smem row stride (elems): 80B ≡ 16 mod 128 -> conflict-free
#define NTHR 128

template <int BM, int BN, int EPI>
__global__ void __launch_bounds__(NTHR, 2)
k_gemm(const __nv_bfloat16* __restrict__ A, const __nv_bfloat16* __restrict__ Bt,
       const float* __restrict__ bias, void* __restrict__ outp,
       const float* __restrict__ resid, int M, int N, int K) {
    constexpr int WMT = BM / 2;
    constexpr int WNT = BN / 2;
    constexpr int NM = WMT / 16;
    constexpr int NN = WNT / 8;
    constexpr int NB = WNT / 16;
    constexpr int AST = BM * KSTR;
    constexpr int BST = BN * KSTR;
    constexpr int NGAP = NM + NB;              // ldmatrix ops per kk-step
    constexpr int NMMA = NM * NN;              // MMAs per kk-step
    constexpr int NAPC = BM * 4 / NTHR;        // A cp.async pieces per thread
    constexpr int NBPC = BN * 4 / NTHR;        // B cp.async pieces per thread
    constexpr int NPC  = NAPC + NBPC;
    constexpr int NSL  = (NPC > NGAP) ? NPC : NGAP;   // interleave slots

    extern __shared__ __align__(16) char smem[];
    __nv_bfloat16* As = reinterpret_cast<__nv_bfloat16*>(smem);   // [4][BM][KSTR]
    __nv_bfloat16* Bs = As + 4 * AST;                             // [4][BN][KSTR]

    const int tid  = threadIdx.x;
    const int lane = tid & 31;
    const int warp = tid >> 5;
    const int wm = warp >> 1;
    const int wn = warp & 1;
    const int bm0 = blockIdx.y * BM;
    const int bn0 = blockIdx.x * BN;
    const int KT = K / BK;
    const int NE = KT / 2;

    float acc[NM][NN][4];
    #pragma unroll
    for (int a = 0; a < NM; a++)
        #pragma unroll
        for (int b = 0; b < NN; b++)
            #pragma unroll
            for (int c = 0; c < 4; c++) acc[a][b][c] = 0.f;

    uint32_t afr[2][NM][4];
    uint32_t bfr[2][NB][4];

    // non-trans B frag tile order: r0=(n0:8,k0:8) r1=(n8:16,k0:8) r2=(n0:8,k8:16) r3=(n8:16,k8:16)
    // m16n8k16 .col B operand for n8-block j of the 16-wide frag: b0 = reg[j], b1 = reg[j+2]
    auto mma_one = [&](int buf, int m) {
        int im = m / NN, in = m % NN;
        mma16816(acc[im][in], afr[buf][im],
                 bfr[buf][in >> 1][in & 1], bfr[buf][in >> 1][(in & 1) + 2]);
    };
    auto ld_gap = [&](int buf, int s, int kk, int g) {
        if (g < NM)
            ldmatrix_x4(afr[buf][g],
                As + s * AST + (wm * WMT + g * 16 + (lane & 15)) * KSTR + kk * 16 + (lane >> 4) * 8);
        else
            ldmatrix_x4(bfr[buf][g - NM],
                Bs + s * BST + (wn * WNT + (g - NM) * 16 + (lane & 15)) * KSTR + kk * 16 + (lane >> 4) * 8);
    };
    auto cp_piece = [&](int kt, int s, int i) {
        if (i < NAPC) {
            int idx = tid + i * NTHR;
            int r = idx >> 2, c = idx & 3;
            cp_async16(As + s * AST + r * KSTR + c * 8, A + (size_t)(bm0 + r) * K + kt * BK + c * 8);
        } else {
            int idx = tid + (i - NAPC) * NTHR;
            int r = idx >> 2, c = idx & 3;
            cp_async16(Bs + s * BST + r * KSTR + c * 8, Bt + (size_t)(bn0 + r) * K + kt * BK + c * 8);
        }
    };
    auto load_burst = [&](int kt, int s) {
        #pragma unroll
        for (int i = 0; i < NPC; i++) cp_piece(kt, s, i);
        cp_commit();
    };
    auto step = [&](int cbuf, int lbuf, int ls, int lkk, int ldkt, int lds, bool docp) {
        #pragma unroll
        for (int g = 0; g < NSL; g++) {
            const int m0 = (g * NMMA) / NSL, m1 = ((g + 1) * NMMA) / NSL;
            #pragma unroll
            for (int m = m0; m < m1; m++) mma_one(cbuf, m);
            if (g < NGAP) ld_gap(lbuf, ls, lkk, g);
            if (docp && g < NPC) cp_piece(ldkt, lds, g);
        }
        if (docp) cp_commit();
    };

    // prologue
    load_burst(0, 0);
    load_burst(1, 1);
    cp_wait<0>();
    __syncthreads();
    #pragma unroll
    for (int g = 0; g < NGAP; g++) ld_gap(0, 0, 0, g);

    for (int e = 0; e < NE; e++) {
        const int p  = e & 1;
        const int s0 = 2 * p, s1 = s0 + 1;
        const int q0 = 2 - 2 * p, q1 = q0 + 1;
        const int ktn = 2 * (e + 1);
        const bool more = (ktn < KT);

        step(0, 1, s0, 1, ktn,     q0, more);
        step(1, 0, s1, 0, ktn + 1, q1, more);
        step(0, 1, s1, 1, 0, 0, false);

        constexpr int HALF = NMMA / 2;
        #pragma unroll
        for (int m = 0; m < HALF; m++) mma_one(1, m);
        if (e + 1 < NE) {
            cp_wait<0>();
            __syncthreads();
        }
        #pragma unroll
        for (int g = 0; g < NGAP; g++) {
            const int m0 = HALF + (g * (NMMA - HALF)) / NGAP;
            const int m1 = HALF + ((g + 1) * (NMMA - HALF)) / NGAP;
            #pragma unroll
            for (int m = m0; m < m1; m++) mma_one(1, m);
            if (e + 1 < NE) ld_gap(0, q0, 0, g);
        }
    }

    // epilogue straight from registers
    #pragma unroll
    for (int im = 0; im < NM; im++) {
        const int r0 = bm0 + wm * WMT + im * 16 + (lane >> 2);
        #pragma unroll
        for (int in = 0; in < NN; in++) {
            const int c0 = bn0 + wn * WNT + in * 8 + (lane & 3) * 2;
            const float bv0 = bias[c0], bv1 = bias[c0 + 1];
            #pragma unroll
            for (int half = 0; half < 2; half++) {
                const int r = r0 + half * 8;
                float v0 = acc[im][in][half * 2 + 0] + bv0;
                float v1 = acc[im][in][half * 2 + 1] + bv1;
                if (EPI == 0) {
                    v0 = v0 >= 0.f ? v0 : 0.2f * v0;
                    v1 = v1 >= 0.f ? v1 : 0.2f * v1;
                    *reinterpret_cast<__nv_bfloat162*>(
                        (__nv_bfloat16*)outp + (size_t)r * N + c0) = __floats2bfloat162_rn(v0, v1);
                } else if (EPI == 1) {
                    float2 o; o.x = v0; o.y = v1;
                    *reinterpret_cast<float2*>((float*)outp + (size_t)r * N + c0) = o;
                } else {
                    float2 xv = *reinterpret_cast<const float2*>(resid + (size_t)r * N + c0);
                    float2 o; o.x = xv.x + 0.1f * v0; o.y = xv.y + 0.1f * v1;
                    *reinterpret_cast<float2*>((float*)outp + (size_t)r * N + c0) = o;
                }
            }
        }
    }
}

// ---------------- launch ----------------
extern "C" void kernel_launch(void* const* d_in, const int* in_sizes, int n_in,
                              void* d_out, int out_size) {
    const float* x        = (const float*)d_in[0];
    const float* t        = (const float*)d_in[1];
    const float* W1       = (const float*)d_in[2];
    const float* b1       = (const float*)d_in[3];
    const float* W2       = (const float*)d_in[4];
    const float* b2       = (const float*)d_in[5];
    const float* W3       = (const float*)d_in[6];
    const float* b3       = (const float*)d_in[7];
    const float* W4       = (const float*)d_in[8];
    const float* b4       = (const float*)d_in[9];
    const float* Wt       = (const float*)d_in[10];
    const float* bt       = (const float*)d_in[11];
    const float* coupling = (const float*)d_in[12];
    const float* freq     = (const float*)d_in[13];
    const float* mu       = (const float*)d_in[14];
    float* out = (float*)d_out;

    void *p_xb, *p_h, *p_h2, *p_osc, *p_comb, *p_W1, *p_W2, *p_W3, *p_W4;
    cudaGetSymbolAddress(&p_xb,   g_xb);
    cudaGetSymbolAddress(&p_h,    g_h);
    cudaGetSymbolAddress(&p_h2,   g_h2);
    cudaGetSymbolAddress(&p_osc,  g_osc);
    cudaGetSymbolAddress(&p_comb, g_comb);
    cudaGetSymbolAddress(&p_W1,   g_W1t);
    cudaGetSymbolAddress(&p_W2,   g_W2t);
    cudaGetSymbolAddress(&p_W3,   g_W3t);
    cudaGetSymbolAddress(&p_W4,   g_W4t);

    // smem sizes (bytes): 4 stages x (BM + BN) rows x KSTR elems x 2B
    const int SM_128 = 4 * (128 + 128) * KSTR * 2;  // 81920
    const int SM_SML = 4 * (32 + 128) * KSTR * 2;   // 51200
    cudaFuncSetAttribute(k_gemm<128, 128, 0>, cudaFuncAttributeMaxDynamicSharedMemorySize, SM_128);
    cudaFuncSetAttribute(k_gemm<128, 128, 2>, cudaFuncAttributeMaxDynamicSharedMemorySize, SM_128);
    cudaFuncSetAttribute(k_gemm<32, 128, 1>,  cudaFuncAttributeMaxDynamicSharedMemorySize, SM_SML);

    // fused prep: x convert + weight transposes + csum (one launch)
    k_prep<<<10497, 256>>>(x, W1, W2, W3, W4, coupling);

    dim3 gBig(HDIM / 128, TOKENS / 128);   // (8, 64) = 512 CTAs
    dim3 gOsc(1, TOKENS / 32);             // (1, 256)

    // h = lrelu(x @ W1 + b1)
    k_gemm<128, 128, 0><<<gBig, NTHR, SM_128>>>((const __nv_bfloat16*)p_xb, (const __nv_bfloat16*)p_W1,
                                                b1, p_h, nullptr, TOKENS, HDIM, HDIM);
    // osc = h @ W2 + b2 (f32)
    k_gemm<32, 128, 1><<<gOsc, NTHR, SM_SML>>>((const __nv_bfloat16*)p_h, (const __nv_bfloat16*)p_W2,
                                               b2, p_osc, nullptr, TOKENS, TWO_N, HDIM);
    // oscillator dynamics -> combined (bf16)
    k_dynamics<<<TOKENS / 8, 256>>>(t, Wt, bt, freq, mu);
    // h2 = lrelu(combined @ W3 + b3)
    k_gemm<128, 128, 0><<<gBig, NTHR, SM_128>>>((const __nv_bfloat16*)p_comb, (const __nv_bfloat16*)p_W3,
                                                b3, p_h2, nullptr, TOKENS, HDIM, TWO_N);
    // out = x + 0.1*(h2 @ W4 + b4)
    k_gemm<128, 128, 2><<<gBig, NTHR, SM_128>>>((const __nv_bfloat16*)p_h2, (const __nv_bfloat16*)p_W4,
                                                b4, out, x, TOKENS, HDIM, HDIM);
}

// round 14
// speedup vs baseline: 1.0504x; 1.0504x over previous
#include <cuda_runtime.h>
#include <cuda_bf16.h>
#include <cstdint>
#include <math.h>

#define TOKENS 8192
#define HDIM   1024
#define NOSC   64
#define TWO_N  128
#define SEQ    2048

// ---------------- scratch (static device memory; no allocations) ----------------
static __device__ __nv_bfloat16 g_xb [TOKENS * HDIM];
static __device__ __nv_bfloat16 g_h  [TOKENS * HDIM];
static __device__ __nv_bfloat16 g_h2 [TOKENS * HDIM];
static __device__ float         g_osc[TOKENS * TWO_N];
static __device__ __nv_bfloat16 g_comb[TOKENS * TWO_N];
static __device__ __nv_bfloat16 g_W1b[HDIM * HDIM];
static __device__ __nv_bfloat16 g_W2b[HDIM * TWO_N];
static __device__ __nv_bfloat16 g_W3b[TWO_N * HDIM];
static __device__ __nv_bfloat16 g_W4b[HDIM * HDIM];
static __device__ float         g_csum[NOSC];

// ---------------- PTX helpers ----------------
__device__ __forceinline__ void cp_async16(void* s, const void* g) {
    uint32_t sa = (uint32_t)__cvta_generic_to_shared(s);
    asm volatile("cp.async.cg.shared.global [%0], [%1], 16;\n" :: "r"(sa), "l"(g));
}
__device__ __forceinline__ void cp_commit() {
    asm volatile("cp.async.commit_group;\n" ::: "memory");
}
template <int N>
__device__ __forceinline__ void cp_wait() {
    asm volatile("cp.async.wait_group %0;\n" :: "n"(N) : "memory");
}
__device__ __forceinline__ void ldmatrix_x4(uint32_t* r, const void* p) {
    uint32_t a = (uint32_t)__cvta_generic_to_shared(p);
    asm volatile("ldmatrix.sync.aligned.m8n8.x4.shared.b16 {%0,%1,%2,%3}, [%4];\n"
        : "=r"(r[0]), "=r"(r[1]), "=r"(r[2]), "=r"(r[3]) : "r"(a));
}
__device__ __forceinline__ void ldmatrix_x4_trans(uint32_t* r, const void* p) {
    uint32_t a = (uint32_t)__cvta_generic_to_shared(p);
    asm volatile("ldmatrix.sync.aligned.m8n8.x4.trans.shared.b16 {%0,%1,%2,%3}, [%4];\n"
        : "=r"(r[0]), "=r"(r[1]), "=r"(r[2]), "=r"(r[3]) : "r"(a));
}
// NON-volatile: ptxas schedules by register dependencies.
__device__ __forceinline__ void mma16816(float* d, const uint32_t* a, uint32_t b0, uint32_t b1) {
    asm("mma.sync.aligned.m16n8k16.row.col.f32.bf16.bf16.f32 "
        "{%0,%1,%2,%3}, {%4,%5,%6,%7}, {%8,%9}, {%0,%1,%2,%3};\n"
        : "+f"(d[0]), "+f"(d[1]), "+f"(d[2]), "+f"(d[3])
        : "r"(a[0]), "r"(a[1]), "r"(a[2]), "r"(a[3]), "r"(b0), "r"(b1));
}

// ---------------- fused prep: x convert + weight converts + csum + osc bias init ----------------
// grid = 8192 (x) + 2304 (weights) + 1 (csum) + 1024 (osc=b2) = 11521 blocks of 256
__global__ void k_prep(const float* __restrict__ x,
                       const float* __restrict__ W1, const float* __restrict__ W2,
                       const float* __restrict__ W3, const float* __restrict__ W4,
                       const float* __restrict__ coupling, const float* __restrict__ b2) {
    const int b = blockIdx.x;
    const int tid = threadIdx.x;
    if (b < 10496) {
        const float* in; __nv_bfloat16* out; int base;
        if (b < 8192)      { in = x;  out = g_xb;  base = b * 1024; }
        else if (b < 9216) { in = W1; out = g_W1b; base = (b - 8192) * 1024; }
        else if (b < 9344) { in = W2; out = g_W2b; base = (b - 9216) * 1024; }
        else if (b < 9472) { in = W3; out = g_W3b; base = (b - 9344) * 1024; }
        else               { in = W4; out = g_W4b; base = (b - 9472) * 1024; }
        int i = base + tid * 4;
        float4 v = *reinterpret_cast<const float4*>(in + i);
        *reinterpret_cast<__nv_bfloat162*>(out + i)     = __floats2bfloat162_rn(v.x, v.y);
        *reinterpret_cast<__nv_bfloat162*>(out + i + 2) = __floats2bfloat162_rn(v.z, v.w);
    } else if (b == 10496) {
        int m = tid;
        if (m < NOSC) {
            float s = 0.f;
            #pragma unroll
            for (int j = 0; j < NOSC; j++) s += coupling[m * NOSC + j];
            g_csum[m] = s;
        }
    } else {
        // osc := b2 broadcast (split-K GEMM2 atomically accumulates on top)
        int i = (b - 10497) * 1024 + tid * 4;
        int c = i & (TWO_N - 1);
        float4 v = *reinterpret_cast<const float4*>(b2 + c);
        *reinterpret_cast<float4*>(g_osc + i) = v;
    }
}

// ---------------- oscillator dynamics: 1 warp per token, 2 osc per lane ----------------
__global__ void k_dynamics(const float* __restrict__ t, const float* __restrict__ Wt,
                           const float* __restrict__ bt, const float* __restrict__ freq,
                           const float* __restrict__ mu_p) {
    const int tok  = blockIdx.x * 8 + (threadIdx.x >> 5);
    const int lane = threadIdx.x & 31;
    const int i0 = lane, i1 = lane + 32;
    __nv_bfloat16* out = g_comb + (size_t)tok * TWO_N;

    if ((tok & (SEQ - 1)) == 0) {
        const float* cur = g_osc + (size_t)tok * TWO_N;
        out[i0]        = __float2bfloat16(cur[i0]);
        out[i1]        = __float2bfloat16(cur[i1]);
        out[NOSC + i0] = __float2bfloat16(cur[NOSC + i0]);
        out[NOSC + i1] = __float2bfloat16(cur[NOSC + i1]);
        return;
    }

    const float* prev = g_osc + (size_t)(tok - 1) * TWO_N;
    float p0 = prev[i0], p1 = prev[i1];
    float a0 = prev[NOSC + i0], a1 = prev[NOSC + i1];
    float sp0, cp0, sp1, cp1;
    sincosf(p0, &sp0, &cp0);
    sincosf(p1, &sp1, &cp1);

    float cs0 = g_csum[i0], cs1 = g_csum[i1];
    float vc = cs0 * cp0 + cs1 * cp1;
    float vs = cs0 * sp0 + cs1 * sp1;
    #pragma unroll
    for (int o = 16; o > 0; o >>= 1) {
        vc += __shfl_xor_sync(0xffffffffu, vc, o);
        vs += __shfl_xor_sync(0xffffffffu, vs, o);
    }

    const float tv = t[tok];
    const float mu = *mu_p;

    float cpl0 = sp0 * vc - cp0 * vs;
    float cpl1 = sp1 * vc - cp1 * vs;
    float d0 = freq[i0] + cpl0 * 0.1f + (tv * Wt[i0] + bt[i0]) * 0.1f;
    float d1 = freq[i1] + cpl1 * 0.1f + (tv * Wt[i1] + bt[i1]) * 0.1f;
    float pn0 = p0 + d0 * 0.1f;
    float pn1 = p1 + d1 * 0.1f;

    float da0 = (mu - 0.1f) * a0 - a0 * a0 * a0;
    float da1 = (mu - 0.1f) * a1 - a1 * a1 * a1;
    float an0 = tanhf(a0 + da0 * 0.1f);
    float an1 = tanhf(a1 + da1 * 0.1f);

    out[i0]        = __float2bfloat16(pn0);
    out[i1]        = __float2bfloat16(pn1);
    out[NOSC + i0] = __float2bfloat16(an0);
    out[NOSC + i1] = __float2bfloat16(an1);
}

// ---------------- tiled bf16 mma.sync GEMM, epoch pipeline + fine-grained interleave ----------------
// 128-thread CTAs, warp grid 2x2, warp tile (BM/2) x (BN/2).
// 4 slots of BK=32 as two pairs; one cp.async.wait+__syncthreads per 64 K.
// blockIdx.z = K-slice index (split-K); K param = slice length.
// EPI: 0 = bias+leaky_relu -> bf16 ; 1 = bias -> f32 ; 2 = resid + 0.1*(acc+bias) -> f32
//      3 = atomicAdd raw acc -> f32 (bias pre-initialized in the output)
#define BK 32
#define ASTR 40     // A smem row stride (elems): 80B ≡ 16 mod 128
#define NTHR 128

template <int BM, int BN, int EPI>
__global__ void __launch_bounds__(NTHR, 2)
k_gemm(const __nv_bfloat16* __restrict__ A, const __nv_bfloat16* __restrict__ B,
       const float* __restrict__ bias, void* __restrict__ outp,
       const float* __restrict__ resid, int M, int N, int K) {
    constexpr int BSTR = BN + 8;
    constexpr int WMT = BM / 2;
    constexpr int WNT = BN / 2;
    constexpr int NM = WMT / 16;
    constexpr int NN = WNT / 8;
    constexpr int NB = WNT / 16;
    constexpr int AST = BM * ASTR;
    constexpr int BST = BK * BSTR;
    constexpr int NGAP = NM + NB;              // ldmatrix ops per kk-step
    constexpr int NMMA = NM * NN;              // MMAs per kk-step
    constexpr int NAPC = BM * 4 / NTHR;        // A cp.async pieces per thread
    constexpr int NBPC = BK * (BN / 8) / NTHR; // B cp.async pieces per thread
    static_assert(NAPC + NBPC == NGAP, "cp pieces must equal ldmatrix gaps");

    extern __shared__ __align__(16) char smem[];
    __nv_bfloat16* As = reinterpret_cast<__nv_bfloat16*>(smem);   // [4][BM][ASTR]
    __nv_bfloat16* Bs = As + 4 * AST;                             // [4][BK][BSTR]

    const int tid  = threadIdx.x;
    const int lane = tid & 31;
    const int warp = tid >> 5;
    const int wm = warp >> 1;
    const int wn = warp & 1;
    const int bm0 = blockIdx.y * BM;
    const int bn0 = blockIdx.x * BN;
    // split-K: shift operand base pointers by this CTA's K-slice
    const int kOff = blockIdx.z * K;
    A += kOff;
    B += (size_t)kOff * N;
    const int KT = K / BK;
    const int NE = KT / 2;

    float acc[NM][NN][4];
    #pragma unroll
    for (int a = 0; a < NM; a++)
        #pragma unroll
        for (int b = 0; b < NN; b++)
            #pragma unroll
            for (int c = 0; c < 4; c++) acc[a][b][c] = 0.f;

    uint32_t afr[2][NM][4];
    uint32_t bfr[2][NB][4];

    auto mma_one = [&](int buf, int m) {
        int im = m / NN, in = m % NN;
        mma16816(acc[im][in], afr[buf][im],
                 bfr[buf][in >> 1][(in & 1) * 2], bfr[buf][in >> 1][(in & 1) * 2 + 1]);
    };
    auto ld_gap = [&](int buf, int s, int kk, int g) {
        if (g < NM)
            ldmatrix_x4(afr[buf][g],
                As + s * AST + (wm * WMT + g * 16 + (lane & 15)) * ASTR + kk * 16 + (lane >> 4) * 8);
        else
            ldmatrix_x4_trans(bfr[buf][g - NM],
                Bs + s * BST + (kk * 16 + (lane & 15)) * BSTR + wn * WNT + (g - NM) * 16 + (lane >> 4) * 8);
    };
    auto cp_piece = [&](int kt, int s, int i) {
        if (i < NAPC) {
            int idx = tid + i * NTHR;
            int r = idx >> 2, c = idx & 3;
            cp_async16(As + s * AST + r * ASTR + c * 8, A + (size_t)(bm0 + r) * (K * gridDim.z) + kt * BK + c * 8);
        } else {
            int idx = tid + (i - NAPC) * NTHR;
            int r = idx / (BN / 8), c = idx % (BN / 8);
            cp_async16(Bs + s * BST + r * BSTR + c * 8, B + (size_t)(kt * BK + r) * N + bn0 + c * 8);
        }
    };
    auto load_burst = [&](int kt, int s) {
        #pragma unroll
        for (int i = 0; i < NGAP; i++) cp_piece(kt, s, i);
        cp_commit();
    };
    auto step = [&](int cbuf, int lbuf, int ls, int lkk, int ldkt, int lds, bool docp) {
        #pragma unroll
        for (int g = 0; g < NGAP; g++) {
            const int m0 = (g * NMMA) / NGAP, m1 = ((g + 1) * NMMA) / NGAP;
            #pragma unroll
            for (int m = m0; m < m1; m++) mma_one(cbuf, m);
            ld_gap(lbuf, ls, lkk, g);
            if (docp) cp_piece(ldkt, lds, g);
        }
        if (docp) cp_commit();
    };

    // prologue
    load_burst(0, 0);
    load_burst(1, 1);
    cp_wait<0>();
    __syncthreads();
    #pragma unroll
    for (int g = 0; g < NGAP; g++) ld_gap(0, 0, 0, g);

    for (int e = 0; e < NE; e++) {
        const int p  = e & 1;
        const int s0 = 2 * p, s1 = s0 + 1;
        const int q0 = 2 - 2 * p, q1 = q0 + 1;
        const int ktn = 2 * (e + 1);
        const bool more = (ktn < KT);

        step(0, 1, s0, 1, ktn,     q0, more);
        step(1, 0, s1, 0, ktn + 1, q1, more);
        step(0, 1, s1, 1, 0, 0, false);

        constexpr int HALF = NMMA / 2;
        #pragma unroll
        for (int m = 0; m < HALF; m++) mma_one(1, m);
        if (e + 1 < NE) {
            cp_wait<0>();
            __syncthreads();
        }
        #pragma unroll
        for (int g = 0; g < NGAP; g++) {
            const int m0 = HALF + (g * (NMMA - HALF)) / NGAP;
            const int m1 = HALF + ((g + 1) * (NMMA - HALF)) / NGAP;
            #pragma unroll
            for (int m = m0; m < m1; m++) mma_one(1, m);
            if (e + 1 < NE) ld_gap(0, q0, 0, g);
        }
    }

    // epilogue straight from registers
    #pragma unroll
    for (int im = 0; im < NM; im++) {
        const int r0 = bm0 + wm * WMT + im * 16 + (lane >> 2);
        #pragma unroll
        for (int in = 0; in < NN; in++) {
            const int c0 = bn0 + wn * WNT + in * 8 + (lane & 3) * 2;
            const float bv0 = (EPI == 3) ? 0.f : bias[c0];
            const float bv1 = (EPI == 3) ? 0.f : bias[c0 + 1];
            #pragma unroll
            for (int half = 0; half < 2; half++) {
                const int r = r0 + half * 8;
                float v0 = acc[im][in][half * 2 + 0] + bv0;
                float v1 = acc[im][in][half * 2 + 1] + bv1;
                if (EPI == 0) {
                    v0 = v0 >= 0.f ? v0 : 0.2f * v0;
                    v1 = v1 >= 0.f ? v1 : 0.2f * v1;
                    *reinterpret_cast<__nv_bfloat162*>(
                        (__nv_bfloat16*)outp + (size_t)r * N + c0) = __floats2bfloat162_rn(v0, v1);
                } else if (EPI == 1) {
                    float2 o; o.x = v0; o.y = v1;
                    *reinterpret_cast<float2*>((float*)outp + (size_t)r * N + c0) = o;
                } else if (EPI == 2) {
                    float2 xv = *reinterpret_cast<const float2*>(resid + (size_t)r * N + c0);
                    float2 o; o.x = xv.x + 0.1f * v0; o.y = xv.y + 0.1f * v1;
                    *reinterpret_cast<float2*>((float*)outp + (size_t)r * N + c0) = o;
                } else {
                    atomicAdd((float*)outp + (size_t)r * N + c0,     v0);
                    atomicAdd((float*)outp + (size_t)r * N + c0 + 1, v1);
                }
            }
        }
    }
}

// ---------------- launch ----------------
extern "C" void kernel_launch(void* const* d_in, const int* in_sizes, int n_in,
                              void* d_out, int out_size) {
    const float* x        = (const float*)d_in[0];
    const float* t        = (const float*)d_in[1];
    const float* W1       = (const float*)d_in[2];
    const float* b1       = (const float*)d_in[3];
    const float* W2       = (const float*)d_in[4];
    const float* b2       = (const float*)d_in[5];
    const float* W3       = (const float*)d_in[6];
    const float* b3       = (const float*)d_in[7];
    const float* W4       = (const float*)d_in[8];
    const float* b4       = (const float*)d_in[9];
    const float* Wt       = (const float*)d_in[10];
    const float* bt       = (const float*)d_in[11];
    const float* coupling = (const float*)d_in[12];
    const float* freq     = (const float*)d_in[13];
    const float* mu       = (const float*)d_in[14];
    float* out = (float*)d_out;

    void *p_xb, *p_h, *p_h2, *p_osc, *p_comb, *p_W1, *p_W2, *p_W3, *p_W4;
    cudaGetSymbolAddress(&p_xb,   g_xb);
    cudaGetSymbolAddress(&p_h,    g_h);
    cudaGetSymbolAddress(&p_h2,   g_h2);
    cudaGetSymbolAddress(&p_osc,  g_osc);
    cudaGetSymbolAddress(&p_comb, g_comb);
    cudaGetSymbolAddress(&p_W1,   g_W1b);
    cudaGetSymbolAddress(&p_W2,   g_W2b);
    cudaGetSymbolAddress(&p_W3,   g_W3b);
    cudaGetSymbolAddress(&p_W4,   g_W4b);

    // smem sizes (bytes)
    const int SM_128 = 4 * (128 * ASTR + BK * (128 + 8)) * 2;  // 75776
    const int SM_SML = 4 * (32  * ASTR + BK * (128 + 8)) * 2;  // 45056
    cudaFuncSetAttribute(k_gemm<128, 128, 0>, cudaFuncAttributeMaxDynamicSharedMemorySize, SM_128);
    cudaFuncSetAttribute(k_gemm<128, 128, 2>, cudaFuncAttributeMaxDynamicSharedMemorySize, SM_128);
    cudaFuncSetAttribute(k_gemm<32, 128, 3>,  cudaFuncAttributeMaxDynamicSharedMemorySize, SM_SML);

    // fused prep: x convert + weight converts + csum + osc bias init (one launch)
    k_prep<<<11521, 256>>>(x, W1, W2, W3, W4, coupling, b2);

    dim3 gBig(HDIM / 128, TOKENS / 128);      // (8, 64) = 512 CTAs
    dim3 gOsc(1, TOKENS / 32, 4);             // (1, 256, 4) split-K x4

    // h = lrelu(x @ W1 + b1)
    k_gemm<128, 128, 0><<<gBig, NTHR, SM_128>>>((const __nv_bfloat16*)p_xb, (const __nv_bfloat16*)p_W1,
                                                b1, p_h, nullptr, TOKENS, HDIM, HDIM);
    // osc += h @ W2 (split-K, atomic; bias pre-initialized by prep)
    k_gemm<32, 128, 3><<<gOsc, NTHR, SM_SML>>>((const __nv_bfloat16*)p_h, (const __nv_bfloat16*)p_W2,
                                               b2, p_osc, nullptr, TOKENS, TWO_N, 256);
    // oscillator dynamics -> combined (bf16)
    k_dynamics<<<TOKENS / 8, 256>>>(t, Wt, bt, freq, mu);
    // h2 = lrelu(combined @ W3 + b3)
    k_gemm<128, 128, 0><<<gBig, NTHR, SM_128>>>((const __nv_bfloat16*)p_comb, (const __nv_bfloat16*)p_W3,
                                                b3, p_h2, nullptr, TOKENS, HDIM, TWO_N);
    // out = x + 0.1*(h2 @ W4 + b4)
    k_gemm<128, 128, 2><<<gBig, NTHR, SM_128>>>((const __nv_bfloat16*)p_h2, (const __nv_bfloat16*)p_W4,
                                                b4, out, x, TOKENS, HDIM, HDIM);
}

// round 15
// speedup vs baseline: 1.1474x; 1.0924x over previous
#include <cuda_runtime.h>
#include <cuda_bf16.h>
#include <cstdint>
#include <math.h>

#define TOKENS 8192
#define HTOK   4096     // tokens per half (2 sequences)
#define HDIM   1024
#define NOSC   64
#define TWO_N  128
#define SEQ    2048

// ---------------- scratch (static device memory; no allocations) ----------------
static __device__ __nv_bfloat16 g_xb [TOKENS * HDIM];
static __device__ __nv_bfloat16 g_h  [TOKENS * HDIM];
static __device__ __nv_bfloat16 g_h2 [TOKENS * HDIM];
static __device__ float         g_osc[TOKENS * TWO_N];
static __device__ __nv_bfloat16 g_comb[TOKENS * TWO_N];
static __device__ __nv_bfloat16 g_W1b[HDIM * HDIM];
static __device__ __nv_bfloat16 g_W2b[HDIM * TWO_N];
static __device__ __nv_bfloat16 g_W3b[TWO_N * HDIM];
static __device__ __nv_bfloat16 g_W4b[HDIM * HDIM];
static __device__ float         g_csum[NOSC];

// ---------------- PTX helpers ----------------
__device__ __forceinline__ void cp_async16(void* s, const void* g) {
    uint32_t sa = (uint32_t)__cvta_generic_to_shared(s);
    asm volatile("cp.async.cg.shared.global [%0], [%1], 16;\n" :: "r"(sa), "l"(g));
}
__device__ __forceinline__ void cp_commit() {
    asm volatile("cp.async.commit_group;\n" ::: "memory");
}
template <int N>
__device__ __forceinline__ void cp_wait() {
    asm volatile("cp.async.wait_group %0;\n" :: "n"(N) : "memory");
}
__device__ __forceinline__ void ldmatrix_x4(uint32_t* r, const void* p) {
    uint32_t a = (uint32_t)__cvta_generic_to_shared(p);
    asm volatile("ldmatrix.sync.aligned.m8n8.x4.shared.b16 {%0,%1,%2,%3}, [%4];\n"
        : "=r"(r[0]), "=r"(r[1]), "=r"(r[2]), "=r"(r[3]) : "r"(a));
}
__device__ __forceinline__ void ldmatrix_x4_trans(uint32_t* r, const void* p) {
    uint32_t a = (uint32_t)__cvta_generic_to_shared(p);
    asm volatile("ldmatrix.sync.aligned.m8n8.x4.trans.shared.b16 {%0,%1,%2,%3}, [%4];\n"
        : "=r"(r[0]), "=r"(r[1]), "=r"(r[2]), "=r"(r[3]) : "r"(a));
}
// NON-volatile: ptxas schedules by register dependencies.
__device__ __forceinline__ void mma16816(float* d, const uint32_t* a, uint32_t b0, uint32_t b1) {
    asm("mma.sync.aligned.m16n8k16.row.col.f32.bf16.bf16.f32 "
        "{%0,%1,%2,%3}, {%4,%5,%6,%7}, {%8,%9}, {%0,%1,%2,%3};\n"
        : "+f"(d[0]), "+f"(d[1]), "+f"(d[2]), "+f"(d[3])
        : "r"(a[0]), "r"(a[1]), "r"(a[2]), "r"(a[3]), "r"(b0), "r"(b1));
}

// ---------------- fused prep: x convert + 4 weight converts + coupling csum ----------------
// grid = 8192 (x) + 2304 (weights) + 1 (csum) = 10497 blocks of 256 threads
__global__ void k_prep(const float* __restrict__ x,
                       const float* __restrict__ W1, const float* __restrict__ W2,
                       const float* __restrict__ W3, const float* __restrict__ W4,
                       const float* __restrict__ coupling) {
    const int b = blockIdx.x;
    if (b < 10496) {
        const float* in; __nv_bfloat16* out; int base;
        if (b < 8192)      { in = x;  out = g_xb;  base = b * 1024; }
        else if (b < 9216) { in = W1; out = g_W1b; base = (b - 8192) * 1024; }
        else if (b < 9344) { in = W2; out = g_W2b; base = (b - 9216) * 1024; }
        else if (b < 9472) { in = W3; out = g_W3b; base = (b - 9344) * 1024; }
        else               { in = W4; out = g_W4b; base = (b - 9472) * 1024; }
        int i = base + threadIdx.x * 4;
        float4 v = *reinterpret_cast<const float4*>(in + i);
        *reinterpret_cast<__nv_bfloat162*>(out + i)     = __floats2bfloat162_rn(v.x, v.y);
        *reinterpret_cast<__nv_bfloat162*>(out + i + 2) = __floats2bfloat162_rn(v.z, v.w);
    } else {
        int m = threadIdx.x;
        if (m < NOSC) {
            float s = 0.f;
            #pragma unroll
            for (int j = 0; j < NOSC; j++) s += coupling[m * NOSC + j];
            g_csum[m] = s;
        }
    }
}

// ---------------- oscillator dynamics: 1 warp per token, 2 osc per lane ----------------
__global__ void k_dynamics(const float* __restrict__ t, const float* __restrict__ Wt,
                           const float* __restrict__ bt, const float* __restrict__ freq,
                           const float* __restrict__ mu_p, int tokBase) {
    const int tok  = tokBase + blockIdx.x * 8 + (threadIdx.x >> 5);
    const int lane = threadIdx.x & 31;
    const int i0 = lane, i1 = lane + 32;
    __nv_bfloat16* out = g_comb + (size_t)tok * TWO_N;

    if ((tok & (SEQ - 1)) == 0) {
        const float* cur = g_osc + (size_t)tok * TWO_N;
        out[i0]        = __float2bfloat16(cur[i0]);
        out[i1]        = __float2bfloat16(cur[i1]);
        out[NOSC + i0] = __float2bfloat16(cur[NOSC + i0]);
        out[NOSC + i1] = __float2bfloat16(cur[NOSC + i1]);
        return;
    }

    const float* prev = g_osc + (size_t)(tok - 1) * TWO_N;
    float p0 = prev[i0], p1 = prev[i1];
    float a0 = prev[NOSC + i0], a1 = prev[NOSC + i1];
    float sp0, cp0, sp1, cp1;
    sincosf(p0, &sp0, &cp0);
    sincosf(p1, &sp1, &cp1);

    float cs0 = g_csum[i0], cs1 = g_csum[i1];
    float vc = cs0 * cp0 + cs1 * cp1;
    float vs = cs0 * sp0 + cs1 * sp1;
    #pragma unroll
    for (int o = 16; o > 0; o >>= 1) {
        vc += __shfl_xor_sync(0xffffffffu, vc, o);
        vs += __shfl_xor_sync(0xffffffffu, vs, o);
    }

    const float tv = t[tok];
    const float mu = *mu_p;

    float cpl0 = sp0 * vc - cp0 * vs;
    float cpl1 = sp1 * vc - cp1 * vs;
    float d0 = freq[i0] + cpl0 * 0.1f + (tv * Wt[i0] + bt[i0]) * 0.1f;
    float d1 = freq[i1] + cpl1 * 0.1f + (tv * Wt[i1] + bt[i1]) * 0.1f;
    float pn0 = p0 + d0 * 0.1f;
    float pn1 = p1 + d1 * 0.1f;

    float da0 = (mu - 0.1f) * a0 - a0 * a0 * a0;
    float da1 = (mu - 0.1f) * a1 - a1 * a1 * a1;
    float an0 = tanhf(a0 + da0 * 0.1f);
    float an1 = tanhf(a1 + da1 * 0.1f);

    out[i0]        = __float2bfloat16(pn0);
    out[i1]        = __float2bfloat16(pn1);
    out[NOSC + i0] = __float2bfloat16(an0);
    out[NOSC + i1] = __float2bfloat16(an1);
}

// ---------------- tiled bf16 mma.sync GEMM, epoch pipeline + fine-grained interleave ----------------
// 128-thread CTAs, warp grid 2x2, warp tile (BM/2) x (BN/2).
// 4 slots of BK=32 as two pairs; one cp.async.wait+__syncthreads per 64 K.
// EPI: 0 = bias+leaky_relu -> bf16 ; 1 = bias -> f32 ; 2 = resid + 0.1*(acc+bias) -> f32
#define BK 32
#define ASTR 40     // A smem row stride (elems): 80B ≡ 16 mod 128
#define NTHR 128

template <int BM, int BN, int EPI>
__global__ void __launch_bounds__(NTHR, 2)
k_gemm(const __nv_bfloat16* __restrict__ A, const __nv_bfloat16* __restrict__ B,
       const float* __restrict__ bias, void* __restrict__ outp,
       const float* __restrict__ resid, int M, int N, int K) {
    constexpr int BSTR = BN + 8;
    constexpr int WMT = BM / 2;
    constexpr int WNT = BN / 2;
    constexpr int NM = WMT / 16;
    constexpr int NN = WNT / 8;
    constexpr int NB = WNT / 16;
    constexpr int AST = BM * ASTR;
    constexpr int BST = BK * BSTR;
    constexpr int NGAP = NM + NB;              // ldmatrix ops per kk-step
    constexpr int NMMA = NM * NN;              // MMAs per kk-step
    constexpr int NAPC = BM * 4 / NTHR;        // A cp.async pieces per thread
    constexpr int NBPC = BK * (BN / 8) / NTHR; // B cp.async pieces per thread
    static_assert(NAPC + NBPC == NGAP, "cp pieces must equal ldmatrix gaps");

    extern __shared__ __align__(16) char smem[];
    __nv_bfloat16* As = reinterpret_cast<__nv_bfloat16*>(smem);   // [4][BM][ASTR]
    __nv_bfloat16* Bs = As + 4 * AST;                             // [4][BK][BSTR]

    const int tid  = threadIdx.x;
    const int lane = tid & 31;
    const int warp = tid >> 5;
    const int wm = warp >> 1;
    const int wn = warp & 1;
    const int bm0 = blockIdx.y * BM;
    const int bn0 = blockIdx.x * BN;
    const int KT = K / BK;
    const int NE = KT / 2;

    float acc[NM][NN][4];
    #pragma unroll
    for (int a = 0; a < NM; a++)
        #pragma unroll
        for (int b = 0; b < NN; b++)
            #pragma unroll
            for (int c = 0; c < 4; c++) acc[a][b][c] = 0.f;

    uint32_t afr[2][NM][4];
    uint32_t bfr[2][NB][4];

    auto mma_one = [&](int buf, int m) {
        int im = m / NN, in = m % NN;
        mma16816(acc[im][in], afr[buf][im],
                 bfr[buf][in >> 1][(in & 1) * 2], bfr[buf][in >> 1][(in & 1) * 2 + 1]);
    };
    auto ld_gap = [&](int buf, int s, int kk, int g) {
        if (g < NM)
            ldmatrix_x4(afr[buf][g],
                As + s * AST + (wm * WMT + g * 16 + (lane & 15)) * ASTR + kk * 16 + (lane >> 4) * 8);
        else
            ldmatrix_x4_trans(bfr[buf][g - NM],
                Bs + s * BST + (kk * 16 + (lane & 15)) * BSTR + wn * WNT + (g - NM) * 16 + (lane >> 4) * 8);
    };
    auto cp_piece = [&](int kt, int s, int i) {
        if (i < NAPC) {
            int idx = tid + i * NTHR;
            int r = idx >> 2, c = idx & 3;
            cp_async16(As + s * AST + r * ASTR + c * 8, A + (size_t)(bm0 + r) * K + kt * BK + c * 8);
        } else {
            int idx = tid + (i - NAPC) * NTHR;
            int r = idx / (BN / 8), c = idx % (BN / 8);
            cp_async16(Bs + s * BST + r * BSTR + c * 8, B + (size_t)(kt * BK + r) * N + bn0 + c * 8);
        }
    };
    auto load_burst = [&](int kt, int s) {
        #pragma unroll
        for (int i = 0; i < NGAP; i++) cp_piece(kt, s, i);
        cp_commit();
    };
    auto step = [&](int cbuf, int lbuf, int ls, int lkk, int ldkt, int lds, bool docp) {
        #pragma unroll
        for (int g = 0; g < NGAP; g++) {
            const int m0 = (g * NMMA) / NGAP, m1 = ((g + 1) * NMMA) / NGAP;
            #pragma unroll
            for (int m = m0; m < m1; m++) mma_one(cbuf, m);
            ld_gap(lbuf, ls, lkk, g);
            if (docp) cp_piece(ldkt, lds, g);
        }
        if (docp) cp_commit();
    };

    // prologue
    load_burst(0, 0);
    load_burst(1, 1);
    cp_wait<0>();
    __syncthreads();
    #pragma unroll
    for (int g = 0; g < NGAP; g++) ld_gap(0, 0, 0, g);

    for (int e = 0; e < NE; e++) {
        const int p  = e & 1;
        const int s0 = 2 * p, s1 = s0 + 1;
        const int q0 = 2 - 2 * p, q1 = q0 + 1;
        const int ktn = 2 * (e + 1);
        const bool more = (ktn < KT);

        step(0, 1, s0, 1, ktn,     q0, more);
        step(1, 0, s1, 0, ktn + 1, q1, more);
        step(0, 1, s1, 1, 0, 0, false);

        constexpr int HALF = NMMA / 2;
        #pragma unroll
        for (int m = 0; m < HALF; m++) mma_one(1, m);
        if (e + 1 < NE) {
            cp_wait<0>();
            __syncthreads();
        }
        #pragma unroll
        for (int g = 0; g < NGAP; g++) {
            const int m0 = HALF + (g * (NMMA - HALF)) / NGAP;
            const int m1 = HALF + ((g + 1) * (NMMA - HALF)) / NGAP;
            #pragma unroll
            for (int m = m0; m < m1; m++) mma_one(1, m);
            if (e + 1 < NE) ld_gap(0, q0, 0, g);
        }
    }

    // epilogue straight from registers
    #pragma unroll
    for (int im = 0; im < NM; im++) {
        const int r0 = bm0 + wm * WMT + im * 16 + (lane >> 2);
        #pragma unroll
        for (int in = 0; in < NN; in++) {
            const int c0 = bn0 + wn * WNT + in * 8 + (lane & 3) * 2;
            const float bv0 = bias[c0], bv1 = bias[c0 + 1];
            #pragma unroll
            for (int half = 0; half < 2; half++) {
                const int r = r0 + half * 8;
                float v0 = acc[im][in][half * 2 + 0] + bv0;
                float v1 = acc[im][in][half * 2 + 1] + bv1;
                if (EPI == 0) {
                    v0 = v0 >= 0.f ? v0 : 0.2f * v0;
                    v1 = v1 >= 0.f ? v1 : 0.2f * v1;
                    *reinterpret_cast<__nv_bfloat162*>(
                        (__nv_bfloat16*)outp + (size_t)r * N + c0) = __floats2bfloat162_rn(v0, v1);
                } else if (EPI == 1) {
                    float2 o; o.x = v0; o.y = v1;
                    *reinterpret_cast<float2*>((float*)outp + (size_t)r * N + c0) = o;
                } else {
                    float2 xv = *reinterpret_cast<const float2*>(resid + (size_t)r * N + c0);
                    float2 o; o.x = xv.x + 0.1f * v0; o.y = xv.y + 0.1f * v1;
                    *reinterpret_cast<float2*>((float*)outp + (size_t)r * N + c0) = o;
                }
            }
        }
    }
}

// ---------------- launch: two captured streams, one half-batch chain each ----------------
extern "C" void kernel_launch(void* const* d_in, const int* in_sizes, int n_in,
                              void* d_out, int out_size) {
    const float* x        = (const float*)d_in[0];
    const float* t        = (const float*)d_in[1];
    const float* W1       = (const float*)d_in[2];
    const float* b1       = (const float*)d_in[3];
    const float* W2       = (const float*)d_in[4];
    const float* b2       = (const float*)d_in[5];
    const float* W3       = (const float*)d_in[6];
    const float* b3       = (const float*)d_in[7];
    const float* W4       = (const float*)d_in[8];
    const float* b4       = (const float*)d_in[9];
    const float* Wt       = (const float*)d_in[10];
    const float* bt       = (const float*)d_in[11];
    const float* coupling = (const float*)d_in[12];
    const float* freq     = (const float*)d_in[13];
    const float* mu       = (const float*)d_in[14];
    float* out = (float*)d_out;

    void *p_xb, *p_h, *p_h2, *p_osc, *p_comb, *p_W1, *p_W2, *p_W3, *p_W4;
    cudaGetSymbolAddress(&p_xb,   g_xb);
    cudaGetSymbolAddress(&p_h,    g_h);
    cudaGetSymbolAddress(&p_h2,   g_h2);
    cudaGetSymbolAddress(&p_osc,  g_osc);
    cudaGetSymbolAddress(&p_comb, g_comb);
    cudaGetSymbolAddress(&p_W1,   g_W1b);
    cudaGetSymbolAddress(&p_W2,   g_W2b);
    cudaGetSymbolAddress(&p_W3,   g_W3b);
    cudaGetSymbolAddress(&p_W4,   g_W4b);

    // lazily-created side stream + events (host resources, created once)
    static cudaStream_t s1 = nullptr;
    static cudaEvent_t evFork = nullptr, evJoin = nullptr;
    if (!s1) {
        cudaStreamCreateWithFlags(&s1, cudaStreamNonBlocking);
        cudaEventCreateWithFlags(&evFork, cudaEventDisableTiming);
        cudaEventCreateWithFlags(&evJoin, cudaEventDisableTiming);
    }

    // smem sizes (bytes)
    const int SM_128 = 4 * (128 * ASTR + BK * (128 + 8)) * 2;  // 75776
    const int SM_SML = 4 * (32  * ASTR + BK * (128 + 8)) * 2;  // 45056
    cudaFuncSetAttribute(k_gemm<128, 128, 0>, cudaFuncAttributeMaxDynamicSharedMemorySize, SM_128);
    cudaFuncSetAttribute(k_gemm<128, 128, 2>, cudaFuncAttributeMaxDynamicSharedMemorySize, SM_128);
    cudaFuncSetAttribute(k_gemm<32, 128, 1>,  cudaFuncAttributeMaxDynamicSharedMemorySize, SM_SML);

    // fused prep (both halves' inputs) on the origin stream
    k_prep<<<10497, 256>>>(x, W1, W2, W3, W4, coupling);

    // fork: side stream joins the capture after prep
    cudaEventRecord(evFork, 0);
    cudaStreamWaitEvent(s1, evFork, 0);

    dim3 gBig(HDIM / 128, HTOK / 128);   // (8, 32) per half
    dim3 gOsc(1, HTOK / 32);             // (1, 128) per half

    // per-half chain on stream `st`, token offset `off`
    auto half_chain = [&](cudaStream_t st, int off) {
        const __nv_bfloat16* xb  = (const __nv_bfloat16*)p_xb + (size_t)off * HDIM;
        __nv_bfloat16* h   = (__nv_bfloat16*)p_h   + (size_t)off * HDIM;
        __nv_bfloat16* h2  = (__nv_bfloat16*)p_h2  + (size_t)off * HDIM;
        float*         osc = (float*)p_osc         + (size_t)off * TWO_N;
        __nv_bfloat16* cmb = (__nv_bfloat16*)p_comb + (size_t)off * TWO_N;

        // h = lrelu(x @ W1 + b1)
        k_gemm<128, 128, 0><<<gBig, NTHR, SM_128, st>>>(xb, (const __nv_bfloat16*)p_W1,
                                                        b1, h, nullptr, HTOK, HDIM, HDIM);
        // osc = h @ W2 + b2 (f32)
        k_gemm<32, 128, 1><<<gOsc, NTHR, SM_SML, st>>>(h, (const __nv_bfloat16*)p_W2,
                                                       b2, osc, nullptr, HTOK, TWO_N, HDIM);
        // oscillator dynamics -> combined (bf16)
        k_dynamics<<<HTOK / 8, 256, 0, st>>>(t, Wt, bt, freq, mu, off);
        // h2 = lrelu(combined @ W3 + b3)
        k_gemm<128, 128, 0><<<gBig, NTHR, SM_128, st>>>(cmb, (const __nv_bfloat16*)p_W3,
                                                        b3, h2, nullptr, HTOK, HDIM, TWO_N);
        // out = x + 0.1*(h2 @ W4 + b4)
        k_gemm<128, 128, 2><<<gBig, NTHR, SM_128, st>>>(h2, (const __nv_bfloat16*)p_W4,
                                                        b4, out + (size_t)off * HDIM,
                                                        x + (size_t)off * HDIM, HTOK, HDIM, HDIM);
    };

    half_chain((cudaStream_t)0, 0);      // sequences 0,1 on the origin stream
    half_chain(s1, HTOK);                // sequences 2,3 on the side stream

    // join: origin stream waits for the side chain
    cudaEventRecord(evJoin, s1);
    cudaStreamWaitEvent((cudaStream_t)0, evJoin, 0);
}

// round 16
// speedup vs baseline: 1.1943x; 1.0409x over previous
#include <cuda_runtime.h>
#include <cuda_bf16.h>
#include <cstdint>
#include <math.h>

#define TOKENS 8192
#define QTOK   2048     // tokens per chain (1 sequence)
#define HDIM   1024
#define NOSC   64
#define TWO_N  128
#define SEQ    2048

// ---------------- scratch (static device memory; no allocations) ----------------
static __device__ __nv_bfloat16 g_xb [TOKENS * HDIM];
static __device__ __nv_bfloat16 g_h  [TOKENS * HDIM];
static __device__ __nv_bfloat16 g_h2 [TOKENS * HDIM];
static __device__ float         g_osc[TOKENS * TWO_N];
static __device__ __nv_bfloat16 g_comb[TOKENS * TWO_N];
static __device__ __nv_bfloat16 g_W1b[HDIM * HDIM];
static __device__ __nv_bfloat16 g_W2b[HDIM * TWO_N];
static __device__ __nv_bfloat16 g_W3b[TWO_N * HDIM];
static __device__ __nv_bfloat16 g_W4b[HDIM * HDIM];
static __device__ float         g_csum[NOSC];

// ---------------- PTX helpers ----------------
__device__ __forceinline__ void cp_async16(void* s, const void* g) {
    uint32_t sa = (uint32_t)__cvta_generic_to_shared(s);
    asm volatile("cp.async.cg.shared.global [%0], [%1], 16;\n" :: "r"(sa), "l"(g));
}
__device__ __forceinline__ void cp_commit() {
    asm volatile("cp.async.commit_group;\n" ::: "memory");
}
template <int N>
__device__ __forceinline__ void cp_wait() {
    asm volatile("cp.async.wait_group %0;\n" :: "n"(N) : "memory");
}
__device__ __forceinline__ void ldmatrix_x4(uint32_t* r, const void* p) {
    uint32_t a = (uint32_t)__cvta_generic_to_shared(p);
    asm volatile("ldmatrix.sync.aligned.m8n8.x4.shared.b16 {%0,%1,%2,%3}, [%4];\n"
        : "=r"(r[0]), "=r"(r[1]), "=r"(r[2]), "=r"(r[3]) : "r"(a));
}
__device__ __forceinline__ void ldmatrix_x4_trans(uint32_t* r, const void* p) {
    uint32_t a = (uint32_t)__cvta_generic_to_shared(p);
    asm volatile("ldmatrix.sync.aligned.m8n8.x4.trans.shared.b16 {%0,%1,%2,%3}, [%4];\n"
        : "=r"(r[0]), "=r"(r[1]), "=r"(r[2]), "=r"(r[3]) : "r"(a));
}
// NON-volatile: ptxas schedules by register dependencies.
__device__ __forceinline__ void mma16816(float* d, const uint32_t* a, uint32_t b0, uint32_t b1) {
    asm("mma.sync.aligned.m16n8k16.row.col.f32.bf16.bf16.f32 "
        "{%0,%1,%2,%3}, {%4,%5,%6,%7}, {%8,%9}, {%0,%1,%2,%3};\n"
        : "+f"(d[0]), "+f"(d[1]), "+f"(d[2]), "+f"(d[3])
        : "r"(a[0]), "r"(a[1]), "r"(a[2]), "r"(a[3]), "r"(b0), "r"(b1));
}

// ---------------- fused prep: x convert + 4 weight converts + coupling csum ----------------
// grid = 8192 (x) + 2304 (weights) + 1 (csum) = 10497 blocks of 256 threads
__global__ void k_prep(const float* __restrict__ x,
                       const float* __restrict__ W1, const float* __restrict__ W2,
                       const float* __restrict__ W3, const float* __restrict__ W4,
                       const float* __restrict__ coupling) {
    const int b = blockIdx.x;
    if (b < 10496) {
        const float* in; __nv_bfloat16* out; int base;
        if (b < 8192)      { in = x;  out = g_xb;  base = b * 1024; }
        else if (b < 9216) { in = W1; out = g_W1b; base = (b - 8192) * 1024; }
        else if (b < 9344) { in = W2; out = g_W2b; base = (b - 9216) * 1024; }
        else if (b < 9472) { in = W3; out = g_W3b; base = (b - 9344) * 1024; }
        else               { in = W4; out = g_W4b; base = (b - 9472) * 1024; }
        int i = base + threadIdx.x * 4;
        float4 v = *reinterpret_cast<const float4*>(in + i);
        *reinterpret_cast<__nv_bfloat162*>(out + i)     = __floats2bfloat162_rn(v.x, v.y);
        *reinterpret_cast<__nv_bfloat162*>(out + i + 2) = __floats2bfloat162_rn(v.z, v.w);
    } else {
        int m = threadIdx.x;
        if (m < NOSC) {
            float s = 0.f;
            #pragma unroll
            for (int j = 0; j < NOSC; j++) s += coupling[m * NOSC + j];
            g_csum[m] = s;
        }
    }
}

// ---------------- oscillator dynamics: 1 warp per token, 2 osc per lane ----------------
__global__ void k_dynamics(const float* __restrict__ t, const float* __restrict__ Wt,
                           const float* __restrict__ bt, const float* __restrict__ freq,
                           const float* __restrict__ mu_p, int tokBase) {
    const int tok  = tokBase + blockIdx.x * 8 + (threadIdx.x >> 5);
    const int lane = threadIdx.x & 31;
    const int i0 = lane, i1 = lane + 32;
    __nv_bfloat16* out = g_comb + (size_t)tok * TWO_N;

    if ((tok & (SEQ - 1)) == 0) {
        const float* cur = g_osc + (size_t)tok * TWO_N;
        out[i0]        = __float2bfloat16(cur[i0]);
        out[i1]        = __float2bfloat16(cur[i1]);
        out[NOSC + i0] = __float2bfloat16(cur[NOSC + i0]);
        out[NOSC + i1] = __float2bfloat16(cur[NOSC + i1]);
        return;
    }

    const float* prev = g_osc + (size_t)(tok - 1) * TWO_N;
    float p0 = prev[i0], p1 = prev[i1];
    float a0 = prev[NOSC + i0], a1 = prev[NOSC + i1];
    float sp0, cp0, sp1, cp1;
    sincosf(p0, &sp0, &cp0);
    sincosf(p1, &sp1, &cp1);

    float cs0 = g_csum[i0], cs1 = g_csum[i1];
    float vc = cs0 * cp0 + cs1 * cp1;
    float vs = cs0 * sp0 + cs1 * sp1;
    #pragma unroll
    for (int o = 16; o > 0; o >>= 1) {
        vc += __shfl_xor_sync(0xffffffffu, vc, o);
        vs += __shfl_xor_sync(0xffffffffu, vs, o);
    }

    const float tv = t[tok];
    const float mu = *mu_p;

    float cpl0 = sp0 * vc - cp0 * vs;
    float cpl1 = sp1 * vc - cp1 * vs;
    float d0 = freq[i0] + cpl0 * 0.1f + (tv * Wt[i0] + bt[i0]) * 0.1f;
    float d1 = freq[i1] + cpl1 * 0.1f + (tv * Wt[i1] + bt[i1]) * 0.1f;
    float pn0 = p0 + d0 * 0.1f;
    float pn1 = p1 + d1 * 0.1f;

    float da0 = (mu - 0.1f) * a0 - a0 * a0 * a0;
    float da1 = (mu - 0.1f) * a1 - a1 * a1 * a1;
    float an0 = tanhf(a0 + da0 * 0.1f);
    float an1 = tanhf(a1 + da1 * 0.1f);

    out[i0]        = __float2bfloat16(pn0);
    out[i1]        = __float2bfloat16(pn1);
    out[NOSC + i0] = __float2bfloat16(an0);
    out[NOSC + i1] = __float2bfloat16(an1);
}

// ---------------- tiled bf16 mma.sync GEMM, epoch pipeline + fine-grained interleave ----------------
// 128-thread CTAs, warp grid 2x2, warp tile (BM/2) x (BN/2).
// 4 slots of BK=32 as two pairs; one cp.async.wait+__syncthreads per 64 K.
// EPI: 0 = bias+leaky_relu -> bf16 ; 1 = bias -> f32 ; 2 = resid + 0.1*(acc+bias) -> f32
#define BK 32
#define ASTR 40     // A smem row stride (elems): 80B ≡ 16 mod 128
#define NTHR 128

template <int BM, int BN, int EPI>
__global__ void __launch_bounds__(NTHR, 2)
k_gemm(const __nv_bfloat16* __restrict__ A, const __nv_bfloat16* __restrict__ B,
       const float* __restrict__ bias, void* __restrict__ outp,
       const float* __restrict__ resid, int M, int N, int K) {
    constexpr int BSTR = BN + 8;
    constexpr int WMT = BM / 2;
    constexpr int WNT = BN / 2;
    constexpr int NM = WMT / 16;
    constexpr int NN = WNT / 8;
    constexpr int NB = WNT / 16;
    constexpr int AST = BM * ASTR;
    constexpr int BST = BK * BSTR;
    constexpr int NGAP = NM + NB;              // ldmatrix ops per kk-step
    constexpr int NMMA = NM * NN;              // MMAs per kk-step
    constexpr int NAPC = BM * 4 / NTHR;        // A cp.async pieces per thread
    constexpr int NBPC = BK * (BN / 8) / NTHR; // B cp.async pieces per thread
    static_assert(NAPC + NBPC == NGAP, "cp pieces must equal ldmatrix gaps");

    extern __shared__ __align__(16) char smem[];
    __nv_bfloat16* As = reinterpret_cast<__nv_bfloat16*>(smem);   // [4][BM][ASTR]
    __nv_bfloat16* Bs = As + 4 * AST;                             // [4][BK][BSTR]

    const int tid  = threadIdx.x;
    const int lane = tid & 31;
    const int warp = tid >> 5;
    const int wm = warp >> 1;
    const int wn = warp & 1;
    const int bm0 = blockIdx.y * BM;
    const int bn0 = blockIdx.x * BN;
    const int KT = K / BK;
    const int NE = KT / 2;

    float acc[NM][NN][4];
    #pragma unroll
    for (int a = 0; a < NM; a++)
        #pragma unroll
        for (int b = 0; b < NN; b++)
            #pragma unroll
            for (int c = 0; c < 4; c++) acc[a][b][c] = 0.f;

    uint32_t afr[2][NM][4];
    uint32_t bfr[2][NB][4];

    auto mma_one = [&](int buf, int m) {
        int im = m / NN, in = m % NN;
        mma16816(acc[im][in], afr[buf][im],
                 bfr[buf][in >> 1][(in & 1) * 2], bfr[buf][in >> 1][(in & 1) * 2 + 1]);
    };
    auto ld_gap = [&](int buf, int s, int kk, int g) {
        if (g < NM)
            ldmatrix_x4(afr[buf][g],
                As + s * AST + (wm * WMT + g * 16 + (lane & 15)) * ASTR + kk * 16 + (lane >> 4) * 8);
        else
            ldmatrix_x4_trans(bfr[buf][g - NM],
                Bs + s * BST + (kk * 16 + (lane & 15)) * BSTR + wn * WNT + (g - NM) * 16 + (lane >> 4) * 8);
    };
    auto cp_piece = [&](int kt, int s, int i) {
        if (i < NAPC) {
            int idx = tid + i * NTHR;
            int r = idx >> 2, c = idx & 3;
            cp_async16(As + s * AST + r * ASTR + c * 8, A + (size_t)(bm0 + r) * K + kt * BK + c * 8);
        } else {
            int idx = tid + (i - NAPC) * NTHR;
            int r = idx / (BN / 8), c = idx % (BN / 8);
            cp_async16(Bs + s * BST + r * BSTR + c * 8, B + (size_t)(kt * BK + r) * N + bn0 + c * 8);
        }
    };
    auto load_burst = [&](int kt, int s) {
        #pragma unroll
        for (int i = 0; i < NGAP; i++) cp_piece(kt, s, i);
        cp_commit();
    };
    auto step = [&](int cbuf, int lbuf, int ls, int lkk, int ldkt, int lds, bool docp) {
        #pragma unroll
        for (int g = 0; g < NGAP; g++) {
            const int m0 = (g * NMMA) / NGAP, m1 = ((g + 1) * NMMA) / NGAP;
            #pragma unroll
            for (int m = m0; m < m1; m++) mma_one(cbuf, m);
            ld_gap(lbuf, ls, lkk, g);
            if (docp) cp_piece(ldkt, lds, g);
        }
        if (docp) cp_commit();
    };

    // prologue
    load_burst(0, 0);
    load_burst(1, 1);
    cp_wait<0>();
    __syncthreads();
    #pragma unroll
    for (int g = 0; g < NGAP; g++) ld_gap(0, 0, 0, g);

    for (int e = 0; e < NE; e++) {
        const int p  = e & 1;
        const int s0 = 2 * p, s1 = s0 + 1;
        const int q0 = 2 - 2 * p, q1 = q0 + 1;
        const int ktn = 2 * (e + 1);
        const bool more = (ktn < KT);

        step(0, 1, s0, 1, ktn,     q0, more);
        step(1, 0, s1, 0, ktn + 1, q1, more);
        step(0, 1, s1, 1, 0, 0, false);

        constexpr int HALF = NMMA / 2;
        #pragma unroll
        for (int m = 0; m < HALF; m++) mma_one(1, m);
        if (e + 1 < NE) {
            cp_wait<0>();
            __syncthreads();
        }
        #pragma unroll
        for (int g = 0; g < NGAP; g++) {
            const int m0 = HALF + (g * (NMMA - HALF)) / NGAP;
            const int m1 = HALF + ((g + 1) * (NMMA - HALF)) / NGAP;
            #pragma unroll
            for (int m = m0; m < m1; m++) mma_one(1, m);
            if (e + 1 < NE) ld_gap(0, q0, 0, g);
        }
    }

    // epilogue straight from registers
    #pragma unroll
    for (int im = 0; im < NM; im++) {
        const int r0 = bm0 + wm * WMT + im * 16 + (lane >> 2);
        #pragma unroll
        for (int in = 0; in < NN; in++) {
            const int c0 = bn0 + wn * WNT + in * 8 + (lane & 3) * 2;
            const float bv0 = bias[c0], bv1 = bias[c0 + 1];
            #pragma unroll
            for (int half = 0; half < 2; half++) {
                const int r = r0 + half * 8;
                float v0 = acc[im][in][half * 2 + 0] + bv0;
                float v1 = acc[im][in][half * 2 + 1] + bv1;
                if (EPI == 0) {
                    v0 = v0 >= 0.f ? v0 : 0.2f * v0;
                    v1 = v1 >= 0.f ? v1 : 0.2f * v1;
                    *reinterpret_cast<__nv_bfloat162*>(
                        (__nv_bfloat16*)outp + (size_t)r * N + c0) = __floats2bfloat162_rn(v0, v1);
                } else if (EPI == 1) {
                    float2 o; o.x = v0; o.y = v1;
                    *reinterpret_cast<float2*>((float*)outp + (size_t)r * N + c0) = o;
                } else {
                    float2 xv = *reinterpret_cast<const float2*>(resid + (size_t)r * N + c0);
                    float2 o; o.x = xv.x + 0.1f * v0; o.y = xv.y + 0.1f * v1;
                    *reinterpret_cast<float2*>((float*)outp + (size_t)r * N + c0) = o;
                }
            }
        }
    }
}

// ---------------- launch: four captured streams, one sequence chain each ----------------
extern "C" void kernel_launch(void* const* d_in, const int* in_sizes, int n_in,
                              void* d_out, int out_size) {
    const float* x        = (const float*)d_in[0];
    const float* t        = (const float*)d_in[1];
    const float* W1       = (const float*)d_in[2];
    const float* b1       = (const float*)d_in[3];
    const float* W2       = (const float*)d_in[4];
    const float* b2       = (const float*)d_in[5];
    const float* W3       = (const float*)d_in[6];
    const float* b3       = (const float*)d_in[7];
    const float* W4       = (const float*)d_in[8];
    const float* b4       = (const float*)d_in[9];
    const float* Wt       = (const float*)d_in[10];
    const float* bt       = (const float*)d_in[11];
    const float* coupling = (const float*)d_in[12];
    const float* freq     = (const float*)d_in[13];
    const float* mu       = (const float*)d_in[14];
    float* out = (float*)d_out;

    void *p_xb, *p_h, *p_h2, *p_osc, *p_comb, *p_W1, *p_W2, *p_W3, *p_W4;
    cudaGetSymbolAddress(&p_xb,   g_xb);
    cudaGetSymbolAddress(&p_h,    g_h);
    cudaGetSymbolAddress(&p_h2,   g_h2);
    cudaGetSymbolAddress(&p_osc,  g_osc);
    cudaGetSymbolAddress(&p_comb, g_comb);
    cudaGetSymbolAddress(&p_W1,   g_W1b);
    cudaGetSymbolAddress(&p_W2,   g_W2b);
    cudaGetSymbolAddress(&p_W3,   g_W3b);
    cudaGetSymbolAddress(&p_W4,   g_W4b);

    // lazily-created side streams + events (host resources, created once)
    static cudaStream_t s[3] = {nullptr, nullptr, nullptr};
    static cudaEvent_t evFork = nullptr;
    static cudaEvent_t evJoin[3] = {nullptr, nullptr, nullptr};
    if (!s[0]) {
        for (int i = 0; i < 3; i++) {
            cudaStreamCreateWithFlags(&s[i], cudaStreamNonBlocking);
            cudaEventCreateWithFlags(&evJoin[i], cudaEventDisableTiming);
        }
        cudaEventCreateWithFlags(&evFork, cudaEventDisableTiming);
    }

    // smem sizes (bytes)
    const int SM_128 = 4 * (128 * ASTR + BK * (128 + 8)) * 2;  // 75776
    const int SM_SML = 4 * (32  * ASTR + BK * (128 + 8)) * 2;  // 45056
    cudaFuncSetAttribute(k_gemm<128, 128, 0>, cudaFuncAttributeMaxDynamicSharedMemorySize, SM_128);
    cudaFuncSetAttribute(k_gemm<128, 128, 2>, cudaFuncAttributeMaxDynamicSharedMemorySize, SM_128);
    cudaFuncSetAttribute(k_gemm<32, 128, 1>,  cudaFuncAttributeMaxDynamicSharedMemorySize, SM_SML);

    // fused prep (all chains' inputs) on the origin stream
    k_prep<<<10497, 256>>>(x, W1, W2, W3, W4, coupling);

    // fork: side streams join the capture after prep
    cudaEventRecord(evFork, 0);
    for (int i = 0; i < 3; i++) cudaStreamWaitEvent(s[i], evFork, 0);

    dim3 gBig(HDIM / 128, QTOK / 128);   // (8, 16) per chain
    dim3 gOsc(1, QTOK / 32);             // (1, 64) per chain

    // per-chain pipeline on stream `st`, token offset `off`
    auto chain = [&](cudaStream_t st, int off) {
        const __nv_bfloat16* xb  = (const __nv_bfloat16*)p_xb + (size_t)off * HDIM;
        __nv_bfloat16* h   = (__nv_bfloat16*)p_h   + (size_t)off * HDIM;
        __nv_bfloat16* h2  = (__nv_bfloat16*)p_h2  + (size_t)off * HDIM;
        float*         osc = (float*)p_osc         + (size_t)off * TWO_N;
        __nv_bfloat16* cmb = (__nv_bfloat16*)p_comb + (size_t)off * TWO_N;

        // h = lrelu(x @ W1 + b1)
        k_gemm<128, 128, 0><<<gBig, NTHR, SM_128, st>>>(xb, (const __nv_bfloat16*)p_W1,
                                                        b1, h, nullptr, QTOK, HDIM, HDIM);
        // osc = h @ W2 + b2 (f32)
        k_gemm<32, 128, 1><<<gOsc, NTHR, SM_SML, st>>>(h, (const __nv_bfloat16*)p_W2,
                                                       b2, osc, nullptr, QTOK, TWO_N, HDIM);
        // oscillator dynamics -> combined (bf16)
        k_dynamics<<<QTOK / 8, 256, 0, st>>>(t, Wt, bt, freq, mu, off);
        // h2 = lrelu(combined @ W3 + b3)
        k_gemm<128, 128, 0><<<gBig, NTHR, SM_128, st>>>(cmb, (const __nv_bfloat16*)p_W3,
                                                        b3, h2, nullptr, QTOK, HDIM, TWO_N);
        // out = x + 0.1*(h2 @ W4 + b4)
        k_gemm<128, 128, 2><<<gBig, NTHR, SM_128, st>>>(h2, (const __nv_bfloat16*)p_W4,
                                                        b4, out + (size_t)off * HDIM,
                                                        x + (size_t)off * HDIM, QTOK, HDIM, HDIM);
    };

    chain((cudaStream_t)0, 0);           // sequence 0 on the origin stream
    chain(s[0], QTOK);                   // sequence 1
    chain(s[1], 2 * QTOK);               // sequence 2
    chain(s[2], 3 * QTOK);               // sequence 3

    // join: origin stream waits for all side chains
    for (int i = 0; i < 3; i++) {
        cudaEventRecord(evJoin[i], s[i]);
        cudaStreamWaitEvent((cudaStream_t)0, evJoin[i], 0);
    }
}